// round 5
// baseline (speedup 1.0000x reference)
#include <cuda_runtime.h>
#include <math.h>

// Problem constants (B, C, H, W) = (2048, 1, 128, 128)
#define NB       2048
#define IMG_PIX  16384     // 128*128
#define CROP_PIX 4096      // 64*64

// Output layout: concatenation of (target, target_cut, target_scene, target_raw)
#define OFF_TARGET 0
#define OFF_CUT    (2048u * 4096u)
#define OFF_SCENE  (2u * 2048u * 4096u)
#define OFF_RAW    (OFF_SCENE + 2048u * 16384u)

// Process one float4 (index i within the image): compute mask, emit all stores.
__device__ __forceinline__ void process4(
    int i, float4 v,
    float sn, float cs, float nsn,
    float xd, float xu, float yd, float yu,
    float* __restrict__ targ, float* __restrict__ cut,
    float* __restrict__ scene, float* __restrict__ raw)
{
    const int r  = i >> 5;         // row 0..127
    const int c0 = (i & 31) << 2;  // col 0,4,...,124

    const float Y  = (float)r - 63.5f;
    const float ty = __fmul_rn(sn, Y);   // sin*Y  (xin term)
    const float cy = __fmul_rn(cs, Y);   // cos*Y  (yin term)

    float tg[4], sc[4];
    const float vv[4] = {v.x, v.y, v.z, v.w};

    #pragma unroll
    for (int k = 0; k < 4; k++) {
        const float X   = (float)(c0 + k) - 63.5f;
        // xin = cos*X + sin*Y ; yin = (-sin)*X + cos*Y  (no FMA, match reference)
        const float xin = __fadd_rn(__fmul_rn(cs,  X), ty);
        const float yin = __fadd_rn(__fmul_rn(nsn, X), cy);
        const float tcol = __fadd_rn(__fadd_rn(xin, 63.5f), 0.5f);
        const float trow = __fadd_rn(__fadd_rn(yin, 63.5f), 0.5f);
        const bool m = (trow >= xd) & (trow < xu) & (tcol >= yd) & (tcol < yu);
        tg[k] = m ? vv[k] : 0.0f;   // image * mask
        sc[k] = m ? 0.0f  : vv[k];  // image * (mask == 0)
    }

    // Streaming stores: outputs are never re-read.
    __stcs(reinterpret_cast<float4*>(raw) + i, v);
    __stcs(reinterpret_cast<float4*>(scene) + i,
           make_float4(sc[0], sc[1], sc[2], sc[3]));

    // Central 64x64 crop [32:96]x[32:96] -> target, target_cut
    if (r >= 32 && r < 96 && c0 >= 32 && c0 < 96) {
        const int ci4 = (((r - 32) << 6) + (c0 - 32)) >> 2;
        __stcs(reinterpret_cast<float4*>(targ) + ci4,
               make_float4(tg[0], tg[1], tg[2], tg[3]));
        float4 cu;
        cu.x = fminf(__fmul_rn(v.x, 2.0f), 1.0f);
        cu.y = fminf(__fmul_rn(v.y, 2.0f), 1.0f);
        cu.z = fminf(__fmul_rn(v.z, 2.0f), 1.0f);
        cu.w = fminf(__fmul_rn(v.w, 2.0f), 1.0f);
        __stcs(reinterpret_cast<float4*>(cut) + ci4, cu);
    }
}

// Handle one full image with the 256 threads of this block.
__device__ __forceinline__ void do_image(
    int b,
    const float* __restrict__ image,
    const float* __restrict__ azimuth,
    float xd, float xu, float yd, float yu,
    float* __restrict__ out)
{
    const float* img   = image + (size_t)b * IMG_PIX;
    float* targ  = out + OFF_TARGET + (size_t)b * CROP_PIX;
    float* cut   = out + OFF_CUT    + (size_t)b * CROP_PIX;
    float* scene = out + OFF_SCENE  + (size_t)b * IMG_PIX;
    float* raw   = out + OFF_RAW    + (size_t)b * IMG_PIX;

    // masks[b] = rotate(box, -azimuth[b]); a = deg2rad(-az)
    const float ang = __fmul_rn(-azimuth[b], 0.017453292519943295f);
    float sn, cs;
    sincosf(ang, &sn, &cs);
    const float nsn = -sn;

    const float4* img4 = reinterpret_cast<const float4*>(img);

    // 4096 float4 per image; 4 groups of 4 front-batched LDG.128 per thread
    // to keep the L1tex wavefront queue deep (MLP_p1 = 4).
    #pragma unroll
    for (int j = 0; j < 4; j++) {
        const int i0 = threadIdx.x + j * 1024;
        const int i1 = i0 + 256;
        const int i2 = i0 + 512;
        const int i3 = i0 + 768;

        const float4 v0 = __ldcs(img4 + i0);
        const float4 v1 = __ldcs(img4 + i1);
        const float4 v2 = __ldcs(img4 + i2);
        const float4 v3 = __ldcs(img4 + i3);

        process4(i0, v0, sn, cs, nsn, xd, xu, yd, yu, targ, cut, scene, raw);
        process4(i1, v1, sn, cs, nsn, xd, xu, yd, yu, targ, cut, scene, raw);
        process4(i2, v2, sn, cs, nsn, xd, xu, yd, yu, targ, cut, scene, raw);
        process4(i3, v3, sn, cs, nsn, xd, xu, yd, yu, targ, cut, scene, raw);
    }
}

__global__ __launch_bounds__(256)
void kd_fused_kernel(const float* __restrict__ image,
                     const float* __restrict__ azimuth,
                     const float* __restrict__ alpha,
                     float* __restrict__ out)
{
    // Box bounds, replicating reference float32 arithmetic (round = half-to-even).
    float a0 = alpha[0], a1 = alpha[1], a2 = alpha[2], a3 = alpha[3];
    float xu = nearbyintf(__fadd_rn(64.0f, __fmul_rn(__fmul_rn(a0, 70.0f), 0.5f)));
    float xd = nearbyintf(__fsub_rn(64.0f, __fmul_rn(__fmul_rn(a1, 70.0f), 0.5f)));
    float yu = nearbyintf(__fadd_rn(64.0f, __fmul_rn(__fmul_rn(a2, 70.0f), 0.5f)));
    float yd = nearbyintf(__fsub_rn(64.0f, __fmul_rn(__fmul_rn(a3, 70.0f), 0.5f)));

    // 1024 blocks, 2 images each -> ~single wave on 148 SMs (no wave tail).
    const int b0 = blockIdx.x * 2;
    do_image(b0,     image, azimuth, xd, xu, yd, yu, out);
    do_image(b0 + 1, image, azimuth, xd, xu, yd, yu, out);
}

extern "C" void kernel_launch(void* const* d_in, const int* in_sizes, int n_in,
                              void* d_out, int out_size)
{
    const float* image   = (const float*)d_in[0];
    const float* azimuth = (const float*)d_in[1];
    const float* alpha   = (const float*)d_in[2];
    float* out = (float*)d_out;

    kd_fused_kernel<<<NB / 2, 256>>>(image, azimuth, alpha, out);
}

// round 6
// speedup vs baseline: 1.0082x; 1.0082x over previous
#include <cuda_runtime.h>
#include <math.h>

// Problem constants (B, C, H, W) = (2048, 1, 128, 128)
#define NB       2048
#define IMG_PIX  16384     // 128*128
#define CROP_PIX 4096      // 64*64

// Output layout: concatenation of (target, target_cut, target_scene, target_raw)
#define OFF_TARGET 0
#define OFF_CUT    (2048u * 4096u)
#define OFF_SCENE  (2u * 2048u * 4096u)
#define OFF_RAW    (OFF_SCENE + 2048u * 16384u)

struct Res4 {
    float4 tg;   // image * mask
    float4 sc;   // image * (mask==0)
};

// Compute mask products for one float4 at image index i.
__device__ __forceinline__ Res4 mask4(
    int i, float4 v,
    float sn, float cs, float nsn,
    float xd, float xu, float yd, float yu)
{
    const int r  = i >> 5;         // row 0..127
    const int c0 = (i & 31) << 2;  // col 0,4,...,124

    const float Y  = (float)r - 63.5f;
    const float ty = __fmul_rn(sn, Y);   // sin*Y  (xin term)
    const float cy = __fmul_rn(cs, Y);   // cos*Y  (yin term)

    float tg[4], sc[4];
    const float vv[4] = {v.x, v.y, v.z, v.w};

    #pragma unroll
    for (int k = 0; k < 4; k++) {
        const float X   = (float)(c0 + k) - 63.5f;
        // xin = cos*X + sin*Y ; yin = (-sin)*X + cos*Y  (no FMA, match reference)
        const float xin = __fadd_rn(__fmul_rn(cs,  X), ty);
        const float yin = __fadd_rn(__fmul_rn(nsn, X), cy);
        const float tcol = __fadd_rn(__fadd_rn(xin, 63.5f), 0.5f);
        const float trow = __fadd_rn(__fadd_rn(yin, 63.5f), 0.5f);
        const bool m = (trow >= xd) & (trow < xu) & (tcol >= yd) & (tcol < yu);
        tg[k] = m ? vv[k] : 0.0f;
        sc[k] = m ? 0.0f  : vv[k];
    }
    Res4 o;
    o.tg = make_float4(tg[0], tg[1], tg[2], tg[3]);
    o.sc = make_float4(sc[0], sc[1], sc[2], sc[3]);
    return o;
}

__device__ __forceinline__ float4 cut4(float4 v)
{
    float4 cu;
    cu.x = fminf(__fmul_rn(v.x, 2.0f), 1.0f);
    cu.y = fminf(__fmul_rn(v.y, 2.0f), 1.0f);
    cu.z = fminf(__fmul_rn(v.z, 2.0f), 1.0f);
    cu.w = fminf(__fmul_rn(v.w, 2.0f), 1.0f);
    return cu;
}

__global__ __launch_bounds__(256, 6)   // cap regs ~40 -> 6 blocks/SM
void kd_fused_kernel(const float* __restrict__ image,
                     const float* __restrict__ azimuth,
                     const float* __restrict__ alpha,
                     float* __restrict__ out)
{
    const int b = blockIdx.x;

    const float* img   = image + (size_t)b * IMG_PIX;
    float* targ  = out + OFF_TARGET + (size_t)b * CROP_PIX;
    float* cut   = out + OFF_CUT    + (size_t)b * CROP_PIX;
    float* scene = out + OFF_SCENE  + (size_t)b * IMG_PIX;
    float* raw   = out + OFF_RAW    + (size_t)b * IMG_PIX;

    // Box bounds, replicating reference float32 arithmetic (round = half-to-even).
    float a0 = alpha[0], a1 = alpha[1], a2 = alpha[2], a3 = alpha[3];
    float xu = nearbyintf(__fadd_rn(64.0f, __fmul_rn(__fmul_rn(a0, 70.0f), 0.5f)));
    float xd = nearbyintf(__fsub_rn(64.0f, __fmul_rn(__fmul_rn(a1, 70.0f), 0.5f)));
    float yu = nearbyintf(__fadd_rn(64.0f, __fmul_rn(__fmul_rn(a2, 70.0f), 0.5f)));
    float yd = nearbyintf(__fsub_rn(64.0f, __fmul_rn(__fmul_rn(a3, 70.0f), 0.5f)));

    // masks[b] = rotate(box, -azimuth[b]); a = deg2rad(-az)
    const float ang = __fmul_rn(-azimuth[b], 0.017453292519943295f);
    float sn, cs;
    sincosf(ang, &sn, &cs);
    const float nsn = -sn;

    const float4* img4 = reinterpret_cast<const float4*>(img);

    // 4096 float4 per image; 2 front-batched LDG.128 per iteration (MLP=2),
    // stores grouped per output stream.
    #pragma unroll 2
    for (int j = 0; j < 8; j++) {
        const int iA = threadIdx.x + j * 512;
        const int iB = iA + 256;

        const float4 vA = __ldcs(img4 + iA);
        const float4 vB = __ldcs(img4 + iB);

        const Res4 rA = mask4(iA, vA, sn, cs, nsn, xd, xu, yd, yu);
        const Res4 rB = mask4(iB, vB, sn, cs, nsn, xd, xu, yd, yu);

        // raw stream (both halves back-to-back)
        __stcs(reinterpret_cast<float4*>(raw) + iA, vA);
        __stcs(reinterpret_cast<float4*>(raw) + iB, vB);
        // scene stream
        __stcs(reinterpret_cast<float4*>(scene) + iA, rA.sc);
        __stcs(reinterpret_cast<float4*>(scene) + iB, rB.sc);

        // Crop region [32:96]x[32:96] -> target, target_cut
        {
            const int r  = iA >> 5;
            const int c0 = (iA & 31) << 2;
            if (r >= 32 && r < 96 && c0 >= 32 && c0 < 96) {
                const int ci4 = (((r - 32) << 6) + (c0 - 32)) >> 2;
                __stcs(reinterpret_cast<float4*>(targ) + ci4, rA.tg);
                __stcs(reinterpret_cast<float4*>(cut)  + ci4, cut4(vA));
            }
        }
        {
            const int r  = iB >> 5;
            const int c0 = (iB & 31) << 2;
            if (r >= 32 && r < 96 && c0 >= 32 && c0 < 96) {
                const int ci4 = (((r - 32) << 6) + (c0 - 32)) >> 2;
                __stcs(reinterpret_cast<float4*>(targ) + ci4, rB.tg);
                __stcs(reinterpret_cast<float4*>(cut)  + ci4, cut4(vB));
            }
        }
    }
}

extern "C" void kernel_launch(void* const* d_in, const int* in_sizes, int n_in,
                              void* d_out, int out_size)
{
    const float* image   = (const float*)d_in[0];
    const float* azimuth = (const float*)d_in[1];
    const float* alpha   = (const float*)d_in[2];
    float* out = (float*)d_out;

    kd_fused_kernel<<<NB, 256>>>(image, azimuth, alpha, out);
}